// round 1
// baseline (speedup 1.0000x reference)
#include <cuda_runtime.h>

#define B_ 4
#define S_ 2048
#define D_ 1024
#define H_ 16
#define HD_ 64
#define OUT_ 256
#define M_ (B_*S_)   // 8192
#define BH_ (B_*H_)  // 64

// Scratch (static device globals — no allocation allowed)
__device__ float g_Q[(size_t)BH_*S_*HD_];   // [BH][S][HD]
__device__ float g_K[(size_t)BH_*S_*HD_];
__device__ float g_V[(size_t)BH_*S_*HD_];
__device__ float g_Ctx[(size_t)M_*D_];      // [B*S][D] with D = h*64+hd

// ---------------------------------------------------------------------------
// Generic 128x128x8 SGEMM: C = A[M,K] @ W[K,N] + bias
// MODE 0: scatter output to heads layout [B,H,S,HD]
// MODE 1: plain row-major [M,N]
// ---------------------------------------------------------------------------
template<int MODE>
__global__ void __launch_bounds__(256, 2) sgemm128(
    const float* __restrict__ A,
    const float* __restrict__ W,
    const float* __restrict__ bias,
    float* __restrict__ C,
    int N, int K)
{
    __shared__ float As[8][128];   // transposed A tile: As[k][m]
    __shared__ float Bs[8][128];   // Bs[k][n]

    const int tid = threadIdx.x;
    const int m0 = blockIdx.y * 128;
    const int n0 = blockIdx.x * 128;
    const int ty = tid >> 4;       // 0..15
    const int tx = tid & 15;       // 0..15

    float acc[8][8];
#pragma unroll
    for (int i = 0; i < 8; i++)
#pragma unroll
        for (int j = 0; j < 8; j++) acc[i][j] = 0.0f;

    const int arow = tid >> 1;           // 0..127
    const int acol = (tid & 1) * 4;      // 0 or 4
    const int brow = tid >> 5;           // 0..7
    const int bcol = (tid & 31) * 4;     // 0..124

    const float* Ap = A + (size_t)(m0 + arow) * K + acol;
    const float* Bp = W + (size_t)brow * N + n0 + bcol;

    for (int k0 = 0; k0 < K; k0 += 8) {
        float4 av = *(const float4*)Ap; Ap += 8;
        float4 bv = *(const float4*)Bp; Bp += (size_t)8 * N;
        As[acol + 0][arow] = av.x;
        As[acol + 1][arow] = av.y;
        As[acol + 2][arow] = av.z;
        As[acol + 3][arow] = av.w;
        *(float4*)&Bs[brow][bcol] = bv;
        __syncthreads();
#pragma unroll
        for (int kk = 0; kk < 8; kk++) {
            float4 a0 = *(const float4*)&As[kk][ty * 4];
            float4 a1 = *(const float4*)&As[kk][64 + ty * 4];
            float4 b0 = *(const float4*)&Bs[kk][tx * 4];
            float4 b1 = *(const float4*)&Bs[kk][64 + tx * 4];
            float a[8] = {a0.x, a0.y, a0.z, a0.w, a1.x, a1.y, a1.z, a1.w};
            float b[8] = {b0.x, b0.y, b0.z, b0.w, b1.x, b1.y, b1.z, b1.w};
#pragma unroll
            for (int i = 0; i < 8; i++)
#pragma unroll
                for (int j = 0; j < 8; j++)
                    acc[i][j] += a[i] * b[j];
        }
        __syncthreads();
    }

    // Epilogue
#pragma unroll
    for (int ih = 0; ih < 2; ih++) {
#pragma unroll
        for (int i = 0; i < 4; i++) {
            int m = m0 + ih * 64 + ty * 4 + i;
            int bb = m >> 11;       // m / 2048
            int s  = m & 2047;
#pragma unroll
            for (int jh = 0; jh < 2; jh++) {
                int nb = n0 + jh * 64 + tx * 4;
                float4 bias4 = *(const float4*)&bias[nb];
                float4 v;
                v.x = acc[ih * 4 + i][jh * 4 + 0] + bias4.x;
                v.y = acc[ih * 4 + i][jh * 4 + 1] + bias4.y;
                v.z = acc[ih * 4 + i][jh * 4 + 2] + bias4.z;
                v.w = acc[ih * 4 + i][jh * 4 + 3] + bias4.w;
                if (MODE == 0) {
                    int h  = nb >> 6;
                    int hd = nb & 63;
                    size_t addr = (((size_t)bb * H_ + h) * S_ + s) * HD_ + hd;
                    *(float4*)&C[addr] = v;
                } else {
                    *(float4*)&C[(size_t)m * N + nb] = v;
                }
            }
        }
    }
}

// ---------------------------------------------------------------------------
// Attention: per CTA: one (b,h), 64 q rows, loop over 32 k-tiles of 64.
// softmax_1: attn = exp(s) / (1 + sum(exp(s)))   (raw exp, matches reference)
// ---------------------------------------------------------------------------
__global__ void __launch_bounds__(256) attn_kernel(
    const float* __restrict__ Q, const float* __restrict__ K,
    const float* __restrict__ V, float* __restrict__ Ctx)
{
    extern __shared__ float sm[];
    float* Qs   = sm;               // [d][q]  64*64
    float* Ks   = Qs + 64 * 64;     // [d][k]  64*66 (padded)
    float* Vs   = Ks + 64 * 66;     // [k][hd] 64*64
    float* Ps   = Vs + 64 * 64;     // [q][k]  64*64
    float* rs_s = Ps + 64 * 64;     // [64]

    const int tid = threadIdx.x;
    const int ty = tid >> 4;        // 0..15
    const int tx = tid & 15;        // 0..15
    const int bh = blockIdx.x;      // 0..63
    const int q0 = blockIdx.y * 64; // 0..2047

    const size_t base = (size_t)bh * S_ * HD_;
    const float* Qg = Q + base + (size_t)q0 * HD_;
    const float* Kg = K + base;
    const float* Vg = V + base;

    // Load Q tile transposed: Qs[d][q]
#pragma unroll
    for (int l = 0; l < 4; l++) {
        int fidx = tid + l * 256;        // float4 index 0..1023
        int r  = fidx >> 4;              // q row 0..63
        int c4 = fidx & 15;              // d/4
        float4 v = *(const float4*)(Qg + r * HD_ + c4 * 4);
        Qs[(c4 * 4 + 0) * 64 + r] = v.x;
        Qs[(c4 * 4 + 1) * 64 + r] = v.y;
        Qs[(c4 * 4 + 2) * 64 + r] = v.z;
        Qs[(c4 * 4 + 3) * 64 + r] = v.w;
    }

    float o[4][4];
#pragma unroll
    for (int i = 0; i < 4; i++)
#pragma unroll
        for (int j = 0; j < 4; j++) o[i][j] = 0.0f;
    float rs[4] = {0.f, 0.f, 0.f, 0.f};

    for (int kt = 0; kt < S_ / 64; kt++) {
        __syncthreads();   // prev iteration done reading Ks/Vs/Ps
        // Load K transposed [d][k] (pad 66) and V natural [k][hd]
#pragma unroll
        for (int l = 0; l < 4; l++) {
            int fidx = tid + l * 256;
            int r  = fidx >> 4;
            int c4 = fidx & 15;
            float4 kv = *(const float4*)(Kg + (size_t)(kt * 64 + r) * HD_ + c4 * 4);
            Ks[(c4 * 4 + 0) * 66 + r] = kv.x;
            Ks[(c4 * 4 + 1) * 66 + r] = kv.y;
            Ks[(c4 * 4 + 2) * 66 + r] = kv.z;
            Ks[(c4 * 4 + 3) * 66 + r] = kv.w;
            float4 vv = *(const float4*)(Vg + (size_t)(kt * 64 + r) * HD_ + c4 * 4);
            *(float4*)&Vs[r * 64 + c4 * 4] = vv;
        }
        __syncthreads();

        // P[q][k] = Q . K  (outer product over d)
        float p[4][4];
#pragma unroll
        for (int i = 0; i < 4; i++)
#pragma unroll
            for (int j = 0; j < 4; j++) p[i][j] = 0.0f;
#pragma unroll 16
        for (int d = 0; d < 64; d++) {
            float4 qv  = *(const float4*)&Qs[d * 64 + ty * 4];
            float2 k01 = *(const float2*)&Ks[d * 66 + tx * 4];
            float2 k23 = *(const float2*)&Ks[d * 66 + tx * 4 + 2];
            float qa[4] = {qv.x, qv.y, qv.z, qv.w};
            float ka[4] = {k01.x, k01.y, k23.x, k23.y};
#pragma unroll
            for (int i = 0; i < 4; i++)
#pragma unroll
                for (int j = 0; j < 4; j++)
                    p[i][j] += qa[i] * ka[j];
        }

        // exp, rowsum (shfl over the 16 tx lanes), store P
#pragma unroll
        for (int i = 0; i < 4; i++) {
            float e0 = __expf(p[i][0] * 0.125f);
            float e1 = __expf(p[i][1] * 0.125f);
            float e2 = __expf(p[i][2] * 0.125f);
            float e3 = __expf(p[i][3] * 0.125f);
            float sum = e0 + e1 + e2 + e3;
            sum += __shfl_xor_sync(0xffffffffu, sum, 1);
            sum += __shfl_xor_sync(0xffffffffu, sum, 2);
            sum += __shfl_xor_sync(0xffffffffu, sum, 4);
            sum += __shfl_xor_sync(0xffffffffu, sum, 8);
            rs[i] += sum;
            float4 ev = {e0, e1, e2, e3};
            *(float4*)&Ps[(ty * 4 + i) * 64 + tx * 4] = ev;
        }
        __syncthreads();

        // O += P @ V
#pragma unroll 4
        for (int k4 = 0; k4 < 16; k4++) {
            float4 pv[4], vv[4];
#pragma unroll
            for (int i = 0; i < 4; i++)
                pv[i] = *(const float4*)&Ps[(ty * 4 + i) * 64 + k4 * 4];
#pragma unroll
            for (int c = 0; c < 4; c++)
                vv[c] = *(const float4*)&Vs[(k4 * 4 + c) * 64 + tx * 4];
#pragma unroll
            for (int i = 0; i < 4; i++) {
                o[i][0] += pv[i].x * vv[0].x + pv[i].y * vv[1].x + pv[i].z * vv[2].x + pv[i].w * vv[3].x;
                o[i][1] += pv[i].x * vv[0].y + pv[i].y * vv[1].y + pv[i].z * vv[2].y + pv[i].w * vv[3].y;
                o[i][2] += pv[i].x * vv[0].z + pv[i].y * vv[1].z + pv[i].z * vv[2].z + pv[i].w * vv[3].z;
                o[i][3] += pv[i].x * vv[0].w + pv[i].y * vv[1].w + pv[i].z * vv[2].w + pv[i].w * vv[3].w;
            }
        }
    }

    // finalize: divide by (1 + rowsum), write ctx in [B,S,D] (D = h*64+hd)
    if (tx == 0) {
#pragma unroll
        for (int i = 0; i < 4; i++) rs_s[ty * 4 + i] = rs[i];
    }
    __syncthreads();

    const int bb = bh >> 4;
    const int h  = bh & 15;
#pragma unroll
    for (int i = 0; i < 4; i++) {
        int q = ty * 4 + i;
        float inv = 1.0f / (1.0f + rs_s[q]);
        float4 v;
        v.x = o[i][0] * inv;
        v.y = o[i][1] * inv;
        v.z = o[i][2] * inv;
        v.w = o[i][3] * inv;
        size_t addr = ((size_t)bb * S_ + q0 + q) * D_ + h * HD_ + tx * 4;
        *(float4*)&Ctx[addr] = v;
    }
}

// ---------------------------------------------------------------------------
extern "C" void kernel_launch(void* const* d_in, const int* in_sizes, int n_in,
                              void* d_out, int out_size)
{
    (void)in_sizes; (void)n_in; (void)out_size;
    const float* query = (const float*)d_in[0];
    const float* key   = (const float*)d_in[1];
    const float* value = (const float*)d_in[2];
    const float* Wq = (const float*)d_in[3];
    const float* bq = (const float*)d_in[4];
    const float* Wk = (const float*)d_in[5];
    const float* bk = (const float*)d_in[6];
    const float* Wv = (const float*)d_in[7];
    const float* bv = (const float*)d_in[8];
    const float* Wf = (const float*)d_in[9];
    const float* bf = (const float*)d_in[10];

    float *Qp, *Kp, *Vp, *Cp;
    cudaGetSymbolAddress((void**)&Qp, g_Q);
    cudaGetSymbolAddress((void**)&Kp, g_K);
    cudaGetSymbolAddress((void**)&Vp, g_V);
    cudaGetSymbolAddress((void**)&Cp, g_Ctx);

    dim3 gProj(D_ / 128, M_ / 128);  // (8, 64)
    sgemm128<0><<<gProj, 256>>>(query, Wq, bq, Qp, D_, D_);
    sgemm128<0><<<gProj, 256>>>(key,   Wk, bk, Kp, D_, D_);
    sgemm128<0><<<gProj, 256>>>(value, Wv, bv, Vp, D_, D_);

    int smem = (64*64 + 64*66 + 64*64 + 64*64 + 64) * (int)sizeof(float);  // 66560 B
    cudaFuncSetAttribute(attn_kernel, cudaFuncAttributeMaxDynamicSharedMemorySize, smem);
    attn_kernel<<<dim3(BH_, S_ / 64), 256, smem>>>(Qp, Kp, Vp, Cp);

    dim3 gOut(OUT_ / 128, M_ / 128); // (2, 64)
    sgemm128<1><<<gOut, 256>>>(Cp, Wf, bf, (float*)d_out, OUT_, D_);
}